// round 3
// baseline (speedup 1.0000x reference)
#include <cuda_runtime.h>
#include <cstdint>

#define BATCH   128
#define IN_DIM  1024
#define OUT_DIM 1024
#define ZD      128

#define NO_     4            // o-values per CTA (main kernel)
#define ISPLIT  2            // i-range splits (main kernel)
#define I_PER   (IN_DIM / ISPLIT)   // 512
#define ITERS   (I_PER / 8)         // 64
#define ROWSZ   132          // padded smem row (floats): bank map 4g+tig conflict-free

// ---------------- helpers ----------------
__device__ __forceinline__ uint32_t f2tf(float f) {
    uint32_t r;
    asm("cvt.rna.tf32.f32 %0, %1;" : "=r"(r) : "f"(f));
    return r;
}

__device__ __forceinline__ void mma_tf32(float* c, const uint32_t* a,
                                         uint32_t b0, uint32_t b1) {
    asm volatile(
        "mma.sync.aligned.m16n8k8.row.col.f32.tf32.tf32.f32 "
        "{%0,%1,%2,%3},{%4,%5,%6,%7},{%8,%9},{%0,%1,%2,%3};"
        : "+f"(c[0]), "+f"(c[1]), "+f"(c[2]), "+f"(c[3])
        : "r"(a[0]), "r"(a[1]), "r"(a[2]), "r"(a[3]), "r"(b0), "r"(b1));
}

// ---------------- K1: out = base_bias + db_b + z @ db_W^T (full overwrite) ----------------
__global__ void __launch_bounds__(256)
k_bias(const float* __restrict__ z, const float* __restrict__ bb,
       const float* __restrict__ dbW, const float* __restrict__ dbb,
       float* __restrict__ out) {
    int idx = blockIdx.x * 256 + threadIdx.x;   // 131072 total
    int b = idx >> 10;
    int o = idx & 1023;
    const float4* zr = (const float4*)(z + (size_t)b * ZD);
    const float4* wr = (const float4*)(dbW + (size_t)o * ZD);
    float acc = bb[o] + dbb[o];
#pragma unroll
    for (int j = 0; j < ZD / 4; j++) {
        float4 zv = zr[j];
        float4 wv = wr[j];
        acc += zv.x * wv.x + zv.y * wv.y + zv.z * wv.z + zv.w * wv.w;
    }
    out[(size_t)b * OUT_DIM + o] = acc;
}

// ---------------- K2: out += x @ (base_weight + dw_b)^T  (fp32 tiled, atomic i-splits) ----------------
__global__ void __launch_bounds__(256)
k_base(const float* __restrict__ x, const float* __restrict__ bw,
       const float* __restrict__ dwb, float* __restrict__ out) {
    __shared__ float xs[128][36];
    __shared__ float wsm[32][36];
    const int t  = threadIdx.x;
    const int o0 = blockIdx.x * 32;   // 32 o-tiles
    const int ib = blockIdx.y * 128;  // 8 i-splits
    const int ty = t >> 3;            // 0..31 -> batch quad
    const int tx = t & 7;             // 0..7  -> o quad
    float acc[4][4] = {};
    for (int it = 0; it < 128; it += 32) {
        {   // stage x tile: 128 rows x 32 cols
            int r = t >> 1;
            int c = (t & 1) * 16;
            const float4* src = (const float4*)(x + (size_t)r * IN_DIM + ib + it + c);
#pragma unroll
            for (int q = 0; q < 4; q++)
                *(float4*)&xs[r][c + 4 * q] = src[q];
        }
        {   // stage w tile: 32 rows x 32 cols (bw + dwb)
            int r = t >> 3;
            int c = (t & 7) * 4;
            size_t off = (size_t)(o0 + r) * IN_DIM + ib + it + c;
            float4 a = *(const float4*)(bw + off);
            float4 b = *(const float4*)(dwb + off);
            *(float4*)&wsm[r][c] = make_float4(a.x + b.x, a.y + b.y, a.z + b.z, a.w + b.w);
        }
        __syncthreads();
#pragma unroll 8
        for (int j = 0; j < 32; j++) {
            float xr[4], wr[4];
#pragma unroll
            for (int q = 0; q < 4; q++) xr[q] = xs[ty * 4 + q][j];
#pragma unroll
            for (int q = 0; q < 4; q++) wr[q] = wsm[tx * 4 + q][j];
#pragma unroll
            for (int p = 0; p < 4; p++)
#pragma unroll
                for (int q = 0; q < 4; q++)
                    acc[p][q] += xr[p] * wr[q];
        }
        __syncthreads();
    }
#pragma unroll
    for (int p = 0; p < 4; p++)
#pragma unroll
        for (int q = 0; q < 4; q++)
            atomicAdd(&out[(size_t)(ty * 4 + p) * OUT_DIM + o0 + tx * 4 + q], acc[p][q]);
}

// ---------------- K3: main hyper-GEMM (z-stationary tf32 mma.sync) ----------------
// out[b, o] += sum_i x[b,i] * ( sum_k dwW[(o*IN+i), k] * z[b,k] )
__global__ void __launch_bounds__(256, 2)
k_main(const float* __restrict__ x, const float* __restrict__ z,
       const float* __restrict__ dwW, float* __restrict__ out) {
    __shared__ __align__(16) uint32_t ws[2][NO_ * 8][ROWSZ];

    const int tid  = threadIdx.x;
    const int w    = tid >> 5;
    const int lane = tid & 31;
    const int g    = lane >> 2;   // groupID
    const int tig  = lane & 3;    // threadID in group
    const int o0   = blockIdx.x * NO_;
    const int ibase = blockIdx.y * I_PER;
    const int b0r = w * 16 + g;
    const int b1r = b0r + 8;

    // --- z A-fragments: loop-invariant, register-resident tf32 ---
    uint32_t zA[16][4];
    {
        const float* z0 = z + (size_t)b0r * ZD;
        const float* z1 = z + (size_t)b1r * ZD;
#pragma unroll
        for (int kb = 0; kb < 16; kb++) {
            int c = kb * 8 + tig;
            zA[kb][0] = f2tf(z0[c]);
            zA[kb][1] = f2tf(z1[c]);
            zA[kb][2] = f2tf(z0[c + 4]);
            zA[kb][3] = f2tf(z1[c + 4]);
        }
    }

    // --- W staging assignment: 2 tasks/thread, each = one (row, kb) 8-float chunk ---
    int trow[2], tkb[2];
    const float* tsrc[2];
#pragma unroll
    for (int q = 0; q < 2; q++) {
        int t = tid + q * 256;
        trow[q] = t >> 4;          // 0..31 : o'*8 + i'
        tkb[q]  = t & 15;          // 0..15
        tsrc[q] = dwW + ((size_t)(o0 + (trow[q] >> 3)) * IN_DIM + ibase + (trow[q] & 7)) * ZD
                      + tkb[q] * 8;
    }

    float4 pre[2][2];
    // prologue load + convert + store buf 0
#pragma unroll
    for (int q = 0; q < 2; q++) {
        const float4* p = (const float4*)tsrc[q];
        pre[q][0] = __ldg(p);
        pre[q][1] = __ldg(p + 1);
    }
#pragma unroll
    for (int q = 0; q < 2; q++) {
        uint32_t* d = &ws[0][trow[q]][tkb[q] * 8];
        *(uint4*)(d)     = make_uint4(f2tf(pre[q][0].x), f2tf(pre[q][0].y),
                                      f2tf(pre[q][0].z), f2tf(pre[q][0].w));
        *(uint4*)(d + 4) = make_uint4(f2tf(pre[q][1].x), f2tf(pre[q][1].y),
                                      f2tf(pre[q][1].z), f2tf(pre[q][1].w));
    }

    float pout[NO_][2];
#pragma unroll
    for (int o = 0; o < NO_; o++) { pout[o][0] = 0.f; pout[o][1] = 0.f; }

    const float* xp0 = x + (size_t)b0r * IN_DIM + ibase + 2 * tig;
    const float* xp1 = x + (size_t)b1r * IN_DIM + ibase + 2 * tig;

#pragma unroll 1
    for (int it = 0; it < ITERS; ++it) {
        // prefetch next W chunk into registers
        if (it + 1 < ITERS) {
#pragma unroll
            for (int q = 0; q < 2; q++) {
                const float4* p = (const float4*)(tsrc[q] + (size_t)(it + 1) * 8 * ZD);
                pre[q][0] = __ldg(p);
                pre[q][1] = __ldg(p + 1);
            }
        }
        __syncthreads();   // current buffer fully staged

        const int buf = it & 1;
        float c[NO_][4];
#pragma unroll
        for (int o = 0; o < NO_; o++)
            c[o][0] = c[o][1] = c[o][2] = c[o][3] = 0.f;

#pragma unroll
        for (int kb = 0; kb < 16; kb++) {
#pragma unroll
            for (int o = 0; o < NO_; o++) {
                uint32_t b0 = ws[buf][o * 8 + g][kb * 8 + tig];
                uint32_t b1 = ws[buf][o * 8 + g][kb * 8 + tig + 4];
                mma_tf32(c[o], zA[kb], b0, b1);
            }
        }

        // epilogue: contract the 8 i-columns against x (fp32)
        float2 xa = *(const float2*)(xp0 + it * 8);
        float2 xb = *(const float2*)(xp1 + it * 8);
#pragma unroll
        for (int o = 0; o < NO_; o++) {
            pout[o][0] += c[o][0] * xa.x + c[o][1] * xa.y;
            pout[o][1] += c[o][2] * xb.x + c[o][3] * xb.y;
        }

        // stage next buffer from prefetch registers
        if (it + 1 < ITERS) {
            const int nb = buf ^ 1;
#pragma unroll
            for (int q = 0; q < 2; q++) {
                uint32_t* d = &ws[nb][trow[q]][tkb[q] * 8];
                *(uint4*)(d)     = make_uint4(f2tf(pre[q][0].x), f2tf(pre[q][0].y),
                                              f2tf(pre[q][0].z), f2tf(pre[q][0].w));
                *(uint4*)(d + 4) = make_uint4(f2tf(pre[q][1].x), f2tf(pre[q][1].y),
                                              f2tf(pre[q][1].z), f2tf(pre[q][1].w));
            }
        }
    }

    // --- reduce over tig (4 lanes hold disjoint i-partials) and accumulate ---
#pragma unroll
    for (int o = 0; o < NO_; o++) {
        float v0 = pout[o][0];
        float v1 = pout[o][1];
        v0 += __shfl_xor_sync(0xffffffffu, v0, 1);
        v0 += __shfl_xor_sync(0xffffffffu, v0, 2);
        v1 += __shfl_xor_sync(0xffffffffu, v1, 1);
        v1 += __shfl_xor_sync(0xffffffffu, v1, 2);
        if (tig == 0) {
            atomicAdd(&out[(size_t)b0r * OUT_DIM + o0 + o], v0);
            atomicAdd(&out[(size_t)b1r * OUT_DIM + o0 + o], v1);
        }
    }
}

// ---------------- launch ----------------
extern "C" void kernel_launch(void* const* d_in, const int* in_sizes, int n_in,
                              void* d_out, int out_size) {
    const float* x   = (const float*)d_in[0];
    const float* z   = (const float*)d_in[1];
    const float* bw  = (const float*)d_in[2];
    const float* dwW = (const float*)d_in[3];
    const float* dwb = (const float*)d_in[4];
    const float* bb  = (const float*)d_in[5];
    const float* dbW = (const float*)d_in[6];
    const float* dbb = (const float*)d_in[7];
    float* out = (float*)d_out;

    // 1) overwrite out with bias terms
    k_bias<<<(BATCH * OUT_DIM) / 256, 256>>>(z, bb, dbW, dbb, out);
    // 2) += x @ (base_weight + dw_b)^T
    k_base<<<dim3(OUT_DIM / 32, 8), 256>>>(x, bw, dwb, out);
    // 3) += hyper-GEMM main term
    k_main<<<dim3(OUT_DIM / NO_, ISPLIT), 256>>>(x, z, dwW, out);
}